// round 15
// baseline (speedup 1.0000x reference)
#include <cuda_runtime.h>
#include <cstdint>

#define BB   64
#define SS   2048
#define HH   256
#define G4   1024

// ---------------- scratch (device globals) -----------------------------------
__device__ float    g_h[2][16 * 1024];   // [buf][bg][k2*8 + b*2 + par]
__device__ unsigned g_flag[128 * 32];    // [(bg*8+hg)*32], 128B apart

// ---------------- f32x2 packed helpers (sm_103a) -----------------------------
__device__ __forceinline__ void ffma2(unsigned long long& d,
                                      unsigned long long a, unsigned long long b) {
    asm("fma.rn.f32x2 %0, %1, %2, %3;" : "=l"(d) : "l"(a), "l"(b), "l"(d));
}
__device__ __forceinline__ unsigned long long pack2(float x, float y) {
    unsigned long long r;
    asm("mov.b64 %0, {%1, %2};" : "=l"(r) : "f"(x), "f"(y));
    return r;
}
__device__ __forceinline__ void unpack2(unsigned long long v, float& a, float& b) {
    asm("mov.b64 {%0, %1}, %2;" : "=f"(a), "=f"(b) : "l"(v));
}
__device__ __forceinline__ float sum2(unsigned long long v) {
    float a, b; unpack2(v, a, b); return a + b;
}
__device__ __forceinline__ void red_release_add(unsigned* p, unsigned v) {
    asm volatile("red.release.gpu.global.add.u32 [%0], %1;"
                 :: "l"(p), "r"(v) : "memory");
}
__device__ __forceinline__ uint32_t smem_u32(const void* p) {
    uint32_t a;
    asm("{ .reg .u64 t; cvta.to.shared.u64 t, %1; cvt.u32.u64 %0, t; }"
        : "=r"(a) : "l"(p));
    return a;
}
__device__ __forceinline__ void cp_async16(uint32_t dst, const void* src) {
    asm volatile("cp.async.cg.shared.global [%0], [%1], 16;"
                 :: "r"(dst), "l"(src) : "memory");
}
__device__ __forceinline__ void cp_async_wait_all() {
    asm volatile("cp.async.commit_group;\n\tcp.async.wait_group 0;" ::: "memory");
}

// ======================= init: zero flags each launch ========================
__global__ void init_flags_kernel() {
    g_flag[threadIdx.x * 32] = 0u;
}

// ======================= fused persistent LSTM ===============================
// 128 CTAs = 16 bg x 8 hg. W_hh in REGISTERS, W_ih in SMEM (float4 layout).
// Window roles: warps 0-3 EW+publish(red.release)+out+x-stage, warps 4-7 full
// xp(t+2) GEMM, warps 8-15 poll+cp.async h pull.
#define GRID2 128
#define T2    512
#define LOOKA 2

__device__ __forceinline__ float sigm_f(float x) { return 1.f / (1.f + __expf(-x)); }
__device__ __forceinline__ float tanh_f(float x) { return 2.f / (1.f + __expf(-2.f * x)) - 1.f; }

// dynamic smem (floats):
//   Wi4  [64*128*4]   128KB   W_ih slice as float4 [k4][r]
//   h2   [2*1024]       8KB   hidden, double buffered
//   redg [4*512]        8KB   gate partials [kq][r][b]
//   redx [512]          2KB   xp results [r][b]
//   x_s  [2*1024]       8KB   x slices, double buffered
#define SM_WI    0
#define SM_H2    (64 * 128 * 4)
#define SM_REDG  (SM_H2 + 2 * 1024)
#define SM_REDX  (SM_REDG + 2048)
#define SM_XS    (SM_REDX + 512)
#define SM_TOTAL ((SM_XS + 2 * 1024) * 4)

__global__ __launch_bounds__(T2, 1)
void lstm_kernel(const float* __restrict__ W_hh, const float* __restrict__ W_ih,
                 const float* __restrict__ b_ih, const float* __restrict__ b_hh,
                 const float* __restrict__ x, float* __restrict__ out,
                 int write_state)
{
    extern __shared__ float sm[];
    float4* Wi4  = (float4*)&sm[SM_WI];
    float*  h2   = &sm[SM_H2];
    float*  redg = &sm[SM_REDG];
    float*  redx = &sm[SM_REDX];
    float*  x_s  = &sm[SM_XS];

    const int tid   = threadIdx.x;
    const int r     = tid & 127;               // local gate row
    const int kq    = tid >> 7;                // k quarter (owns batch kq's xp)
    const int lane  = tid & 31;
    const int wid   = tid >> 5;
    const int bg    = blockIdx.x >> 3;
    const int hg    = blockIdx.x & 7;
    const int bbase = bg * 4;
    const int jbase = hg * 32;
    const int row   = (r >> 5) * 256 + jbase + (r & 31);  // global weight row

    // ---- W_hh slice into registers: 32 f32x2 pairs over quarter kq ----
    unsigned long long w[32];
    {
        const float2* wp = (const float2*)&W_hh[(long)row * 256 + kq * 64];
#pragma unroll
        for (int i = 0; i < 32; i++) {
            float2 f = wp[i];
            w[i] = pack2(f.x, f.y);
        }
    }
    // ---- W_ih slice into smem as float4: Wi4[k4][r] ----
    {
        const float4* wp = (const float4*)&W_ih[(long)row * 256];
#pragma unroll 4
        for (int i = 0; i < 16; i++)
            Wi4[(kq * 16 + i) * 128 + r] = wp[kq * 16 + i];
    }
    const float breg = b_ih[row] + b_hh[row];

    unsigned* const my_flag = &g_flag[(bg * 8 + hg) * 32];
    const uint32_t h2_a = smem_u32(&h2[0]);

    // h(-1) = 0 in buffer 0
    *(float2*)&h2[tid * 2] = make_float2(0.f, 0.f);
    __syncthreads();

    // ================= warmup: xp(0), xp(1) into regs; stage x(2) ============
    float xp0 = 0.f, xp1 = 0.f;
#pragma unroll
    for (int ws = 0; ws < LOOKA; ws++) {
        if (tid < 128) {
#pragma unroll
            for (int half = 0; half < 2; half++) {
                int u = tid + half * 128;
                int b = u >> 6, gq = u & 63;
                float4 v = *(const float4*)&x[((long)(bbase + b) * SS + ws) * 256 + gq * 4];
                float* xb = &x_s[(ws & 1) * 1024];
                *(float2*)&xb[(2 * gq) * 8 + b * 2]     = make_float2(v.x, v.y);
                *(float2*)&xb[(2 * gq + 1) * 8 + b * 2] = make_float2(v.z, v.w);
            }
        }
        __syncthreads();
        if (wid >= 4 && wid < 8) {
            const int rr = tid - 128;
            unsigned long long a0 = 0ull, a1 = 0ull, a2 = 0ull, a3 = 0ull;
            const float* xb = &x_s[(ws & 1) * 1024];
#pragma unroll 8
            for (int k4 = 0; k4 < 64; k4++) {
                ulonglong2 wi = *(const ulonglong2*)&Wi4[k4 * 128 + rr];
                const float* xc = xb + k4 * 16;
                ulonglong2 lo0 = *(const ulonglong2*)(xc);
                ulonglong2 hi0 = *(const ulonglong2*)(xc + 4);
                ffma2(a0, wi.x, lo0.x); ffma2(a1, wi.x, lo0.y);
                ffma2(a2, wi.x, hi0.x); ffma2(a3, wi.x, hi0.y);
                ulonglong2 lo1 = *(const ulonglong2*)(xc + 8);
                ulonglong2 hi1 = *(const ulonglong2*)(xc + 12);
                ffma2(a0, wi.y, lo1.x); ffma2(a1, wi.y, lo1.y);
                ffma2(a2, wi.y, hi1.x); ffma2(a3, wi.y, hi1.y);
            }
            *(float4*)&redx[rr * 4] = make_float4(sum2(a0), sum2(a1), sum2(a2), sum2(a3));
        }
        __syncthreads();
        float nv = breg + redx[r * 4 + kq];
        if (ws == 0) xp0 = nv; else xp1 = nv;
        __syncthreads();
    }
    if (tid < 128) {   // stage x(2) into buf 0 (step 0 window reads buf t&1=0)
#pragma unroll
        for (int half = 0; half < 2; half++) {
            int u = tid + half * 128;
            int b = u >> 6, gq = u & 63;
            float4 v = *(const float4*)&x[((long)(bbase + b) * SS + LOOKA) * 256 + gq * 4];
            float* xb = &x_s[0];
            *(float2*)&xb[(2 * gq) * 8 + b * 2]     = make_float2(v.x, v.y);
            *(float2*)&xb[(2 * gq + 1) * 8 + b * 2] = make_float2(v.z, v.w);
        }
    }
    __syncthreads();

    float c_reg = 0.f, h_last = 0.f;

    for (int t = 0; t < SS; t++) {
        const int p = t & 1;
        const float xp = xp0;
        const bool do_x = (t + LOOKA < SS);

        // ---- gates k-loop: W_hh regs x h2[p] (broadcast), packed parity ----
        {
            unsigned long long a0 = 0ull, a1 = 0ull, a2 = 0ull, a3 = 0ull;
            const float* hb = &h2[p * 1024 + kq * 256];
#pragma unroll
            for (int k2 = 0; k2 < 32; k2++) {
                ulonglong2 lo = *(const ulonglong2*)(hb + k2 * 8);
                ulonglong2 hi = *(const ulonglong2*)(hb + k2 * 8 + 4);
                ffma2(a0, w[k2], lo.x); ffma2(a1, w[k2], lo.y);
                ffma2(a2, w[k2], hi.x); ffma2(a3, w[k2], hi.y);
            }
            float4 part = make_float4(sum2(a0), sum2(a1), sum2(a2), sum2(a3));
            ((float*)&part)[kq] += xp;
            *(float4*)&redg[kq * 512 + r * 4] = part;
        }
        __syncthreads();                                   // sync A

        // ============== WINDOW: three concurrent warp roles ==================
        // ---- warps 0-3: EW + h store + publish FIRST, then out + x stage ----
        if (tid < 128) {
            const int b = tid >> 5, j = tid & 31;
            float g[4];
#pragma unroll
            for (int gi = 0; gi < 4; gi++) {
                const int lr = gi * 32 + j;
                g[gi] = (redg[0 * 512 + lr * 4 + b] + redg[1 * 512 + lr * 4 + b]) +
                        (redg[2 * 512 + lr * 4 + b] + redg[3 * 512 + lr * 4 + b]);
            }
            float iv = sigm_f(g[0]);
            float fv = sigm_f(g[1]);
            float gv = tanh_f(g[2]);
            float ov = sigm_f(g[3]);
            c_reg = fv * c_reg + iv * gv;
            float hn = ov * tanh_f(c_reg);
            h_last = hn;
            const int kh = jbase + j;
            g_h[p ^ 1][bg * 1024 + (kh >> 1) * 8 + b * 2 + (kh & 1)] = hn;
            asm volatile("bar.sync 7, 128;" ::: "memory");   // h stores done
            if (tid == 0 && t + 1 < SS)
                red_release_add(my_flag, 1u);                // publish ASAP
            out[(((long)(bbase + b)) * SS + t) * HH + jbase + j] = hn;
            // stage x(t+1+LOOKA) into the other buffer
            if (t + 1 + LOOKA < SS) {
#pragma unroll
                for (int half = 0; half < 2; half++) {
                    int u = tid + half * 128;
                    int b2 = u >> 6, gq = u & 63;
                    float4 v = *(const float4*)
                        &x[((long)(bbase + b2) * SS + (t + 1 + LOOKA)) * 256 + gq * 4];
                    float* xb = &x_s[((t + 1) & 1) * 1024];
                    *(float2*)&xb[(2 * gq) * 8 + b2 * 2]     = make_float2(v.x, v.y);
                    *(float2*)&xb[(2 * gq + 1) * 8 + b2 * 2] = make_float2(v.z, v.w);
                }
            }
        }

        // ---- warps 4-7: full-k xp(t+LOOKA) GEMM (thread = one row) ----
        if (do_x && wid >= 4 && wid < 8) {
            const int rr = tid - 128;
            unsigned long long a0 = 0ull, a1 = 0ull, a2 = 0ull, a3 = 0ull;
            const float* xb = &x_s[(t & 1) * 1024];
#pragma unroll 8
            for (int k4 = 0; k4 < 64; k4++) {
                ulonglong2 wi = *(const ulonglong2*)&Wi4[k4 * 128 + rr];
                const float* xc = xb + k4 * 16;
                ulonglong2 lo0 = *(const ulonglong2*)(xc);
                ulonglong2 hi0 = *(const ulonglong2*)(xc + 4);
                ffma2(a0, wi.x, lo0.x); ffma2(a1, wi.x, lo0.y);
                ffma2(a2, wi.x, hi0.x); ffma2(a3, wi.x, hi0.y);
                ulonglong2 lo1 = *(const ulonglong2*)(xc + 8);
                ulonglong2 hi1 = *(const ulonglong2*)(xc + 12);
                ffma2(a0, wi.y, lo1.x); ffma2(a1, wi.y, lo1.y);
                ffma2(a2, wi.y, hi1.x); ffma2(a3, wi.y, hi1.y);
            }
            *(float4*)&redx[rr * 4] = make_float4(sum2(a0), sum2(a1), sum2(a2), sum2(a3));
        }

        // ---- warps 8-15: poll peer flag, cp.async its h chunk into h2[p^1] --
        if (t + 1 < SS && wid >= 8) {
            const int peer = wid - 8;
            if (lane == 0) {
                const unsigned* fp = &g_flag[(bg * 8 + peer) * 32];
                while (*((volatile unsigned*)fp) < (unsigned)(t + 1)) { }
            }
            __syncwarp();
            cp_async16(h2_a + (uint32_t)(((p ^ 1) * 1024 + peer * 128 + lane * 4) * 4),
                       &g_h[p ^ 1][bg * 1024 + peer * 128 + lane * 4]);
            cp_async_wait_all();
        }
        __syncthreads();                                   // sync C

        // ---- xp ring shift (redx safe: next write is after next sync A) ----
        if (do_x) {
            float nv = breg + redx[r * 4 + kq];
            xp0 = xp1; xp1 = nv;
        } else {
            xp0 = xp1;
        }
    }

    if (write_state && tid < 128) {
        const int b = tid >> 5, j = tid & 31;
        const long hoff = (long)BB * SS * HH;
        out[hoff +           (bbase + b) * HH + jbase + j] = h_last;
        out[hoff + BB * HH + (bbase + b) * HH + jbase + j] = c_reg;
    }
}

// ============================= launch ========================================
extern "C" void kernel_launch(void* const* d_in, const int* in_sizes, int n_in,
                              void* d_out, int out_size)
{
    const float* x    = (const float*)d_in[0];
    const float* W_ih = (const float*)d_in[1];
    const float* W_hh = (const float*)d_in[2];
    const float* b_ih = (const float*)d_in[3];
    const float* b_hh = (const float*)d_in[4];
    float* out = (float*)d_out;

    init_flags_kernel<<<1, 128>>>();

    cudaFuncSetAttribute(lstm_kernel,
                         cudaFuncAttributeMaxDynamicSharedMemorySize, SM_TOTAL);
    const long full = (long)BB * SS * HH + 2L * BB * HH;
    int write_state = ((long)out_size >= full) ? 1 : 0;
    lstm_kernel<<<GRID2, T2, SM_TOTAL>>>(W_hh, W_ih, b_ih, b_hh, x, out,
                                         write_state);
}